// round 7
// baseline (speedup 1.0000x reference)
#include <cuda_runtime.h>

// Problem constants
#define B_ 8
#define S_ 4096
#define D_ 1024
#define A_ 3
#define C_ 2
#define K_ 64
#define ROWS_TOTAL (B_ * S_)      // 32768
#define NPOS (S_ * A_)            // 12288 flat (seq, anchor) positions per batch
#define MARGIN_ 5.0f

// Output layout: [loss(1) | predict_label(B*S*A) | total_idx(B*K*3) | candidate_label(B*K)]
#define OFF_PRED 1
#define OFF_TIDX (1 + ROWS_TOTAL * A_)           // 98305
#define OFF_CAND (OFF_TIDX + B_ * K_ * 3)        // 99841

// Device scratch (no allocation allowed)
__device__ float    g_logits[ROWS_TOTAL * 6];    // (B*S, A*C) logits
__device__ float    g_losspart[B_];
__device__ unsigned g_done;                      // select-block completion counter

// ---------------------------------------------------------------------------
// Packed f32x2 helpers (Blackwell FFMA2 — PTX-only path)
// ---------------------------------------------------------------------------
__device__ __forceinline__ void ffma2(unsigned long long& a,
                                      unsigned long long x,
                                      unsigned long long w) {
    asm("fma.rn.f32x2 %0, %1, %2, %0;" : "+l"(a) : "l"(x), "l"(w));
}
__device__ __forceinline__ unsigned long long packf2(float lo, float hi) {
    unsigned long long r;
    asm("mov.b64 %0, {%1, %2};" : "=l"(r) : "f"(lo), "f"(hi));
    return r;
}
__device__ __forceinline__ void unpackf2(unsigned long long v, float& lo, float& hi) {
    asm("mov.b64 {%0, %1}, %2;" : "=f"(lo), "=f"(hi) : "l"(v));
}
__device__ __forceinline__ void cp_async16(unsigned smem_addr, const void* gptr) {
    asm volatile("cp.async.cg.shared.global [%0], [%1], 16;"
                 :: "r"(smem_addr), "l"(gptr) : "memory");
}

// ---------------------------------------------------------------------------
// Kernel 1: logits = X @ W + b  and predict_label epilogue
// Row-per-thread. X double-buffer staged via cp.async (prefetch chunk c+1
// while computing chunk c). W transposed in smem as Wt[k][d] so the d-pair
// (w[d][k], w[d+1][k]) is one b64 and the dot product runs on packed
// fma.rn.f32x2 (2 FMAs/instr). Accumulators are lane-split partial sums
// (even d in .lo, odd d in .hi), combined once in the epilogue.
// 256 blocks x 90.6KB smem -> 2 blocks/SM, single wave on 148+ SMs.
// ---------------------------------------------------------------------------
#define GT 128                    // threads per block == rows per block
#define GCH 64                    // d-chunk (floats) per stage
#define GNCH (D_ / GCH)           // 16 chunks
#define XS_CH_F4 (16 * (GT + 1))                 // float4 slots per buffer
#define XS_BYTES (2 * XS_CH_F4 * 16)             // 66048 (double buffer)
#define GEMM_SMEM (XS_BYTES + 6 * D_ * 4)        // + Wt 24576 = 90624

__global__ void __launch_bounds__(GT) gemm_kernel(const float4* __restrict__ X4,
                                                  const float*  __restrict__ W,
                                                  const float*  __restrict__ bias,
                                                  float* __restrict__ out) {
    extern __shared__ char smem_raw[];
    float4* Xs = (float4*)smem_raw;                              // [2][16][GT+1]
    float*  Wt = (float*)(smem_raw + XS_BYTES);                  // [6][D_]
    const unsigned long long* __restrict__ Wt64 =
        (const unsigned long long*)Wt;
    const unsigned xs_base = (unsigned)__cvta_generic_to_shared(Xs);

    const int tid  = threadIdx.x;
    const int row0 = blockIdx.x * GT;

    // Stage W transposed: Wt[k][d] = W[d*6 + k]
    for (int i = tid; i < D_ * 6; i += GT) {
        int d = i / 6;
        int k = i - 6 * d;
        Wt[k * D_ + d] = W[i];
    }

    unsigned long long acc2[6];
    #pragma unroll
    for (int k = 0; k < 6; ++k) acc2[k] = 0ull;   // (+0.0f, +0.0f)

    // Per-thread source/dest for the 16 cp.async of a chunk: element
    // i = it*GT + tid -> row r = i>>4, j = i&15. Lanes 0-15 fetch one row's
    // 256B segment (coalesced), lanes 16-31 the next row's.
    auto issue_chunk = [&](int c, int buf) {
        #pragma unroll
        for (int it = 0; it < 16; ++it) {
            int i = it * GT + tid;
            int r = i >> 4;
            int j = i & 15;
            unsigned dst = xs_base + (unsigned)((buf * XS_CH_F4 + j * (GT + 1) + r) * 16);
            cp_async16(dst, X4 + (size_t)(row0 + r) * (D_ / 4) + c * 16 + j);
        }
        asm volatile("cp.async.commit_group;" ::: "memory");
    };

    issue_chunk(0, 0);

    for (int c = 0; c < GNCH; ++c) {
        if (c + 1 < GNCH) {
            issue_chunk(c + 1, (c + 1) & 1);
            asm volatile("cp.async.wait_group 1;" ::: "memory");   // chunk c done
        } else {
            asm volatile("cp.async.wait_group 0;" ::: "memory");
        }
        __syncthreads();   // chunk c visible to all; covers Wt on first iter

        const float4* Xb = Xs + (c & 1) * XS_CH_F4;
        #pragma unroll
        for (int j = 0; j < 16; ++j) {
            float4 xv = Xb[j * (GT + 1) + tid];
            unsigned long long x01 = packf2(xv.x, xv.y);
            unsigned long long x23 = packf2(xv.z, xv.w);
            const int wb = (c * GCH + j * 4) >> 1;        // ull index within k-row
            #pragma unroll
            for (int k = 0; k < 6; ++k) {
                ulonglong2 wv = *reinterpret_cast<const ulonglong2*>(
                    Wt64 + k * (D_ / 2) + wb);            // 16B-aligned broadcast
                ffma2(acc2[k], x01, wv.x);
                ffma2(acc2[k], x23, wv.y);
            }
        }
        __syncthreads();   // buffer c&1 free before chunk c+2 overwrites it
    }

    // Epilogue: combine lane partials, bias add, store logits (3x STG.64),
    // predict_label (argmax over C=2, tie -> 0)
    const int row = row0 + tid;
    float l[6];
    #pragma unroll
    for (int k = 0; k < 6; ++k) {
        float lo, hi;
        unpackf2(acc2[k], lo, hi);
        l[k] = lo + hi + bias[k];
    }

    float2* lg2 = (float2*)(g_logits + (size_t)row * 6);   // 24B stride, 8B aligned
    lg2[0] = make_float2(l[0], l[1]);
    lg2[1] = make_float2(l[2], l[3]);
    lg2[2] = make_float2(l[4], l[5]);

    float* op = out + OFF_PRED + (size_t)row * 3;
    op[0] = (l[1] > l[0]) ? 1.f : 0.f;
    op[1] = (l[3] > l[2]) ? 1.f : 0.f;
    op[2] = (l[5] > l[4]) ? 1.f : 0.f;
}

// ---------------------------------------------------------------------------
// Kernel 2: per-batch exact top-K over lm[...,1] where positives (label==1)
// are forced to 2.0 (> any sigmoid), tie -> lower index first.
//
// FAST PATH (positives >= K, the overwhelmingly common case): the top-K is
// exactly the K lowest-index positive positions -> stream compaction.
// Contiguous per-thread chunks (chunk order == index order), block exclusive
// scan of positive counts, ranked emit of the first K positives.
//
// FALLBACK (positives < K): exact iterative block argmax over 64-bit keys
// (value_key << 32) | (0xFFFFFFFF - idx), identical to jax.lax.top_k order.
//
// Then writes total_idx, candidate_label, per-batch loss partial; the LAST
// finishing block folds the B partials in fixed order into out[0] and resets
// the counter (graph-replay safe). Label dtype (int64 vs int32) sniffed from
// the buffer's odd 32-bit words (int64 0/1 labels -> all high halves zero).
// ---------------------------------------------------------------------------
#define ST 256
#define SCH (NPOS / ST)           // 48 indices per thread chunk
#define SEL_SMEM (NPOS * 8 + 8 * 8 + K_ * 8 + K_ * 4 + 16)

__device__ __forceinline__ unsigned long long sel_scan_max(
        const unsigned long long* keys, int tid) {
    unsigned long long m = 0ull;
    #pragma unroll 8
    for (int i = 0; i < NPOS / ST; ++i) {
        unsigned long long v = keys[tid + i * ST];
        if (v > m) m = v;
    }
    return m;
}

__global__ void __launch_bounds__(ST) select_kernel(const void* __restrict__ labels_raw,
                                                    float* __restrict__ out) {
    extern __shared__ char sraw[];
    unsigned long long* keys    = (unsigned long long*)sraw;        // [NPOS] (fallback only)
    unsigned long long* wmax    = keys + NPOS;                      // [8]
    unsigned long long* winners = wmax + 8;                         // [K_]
    unsigned*           spos    = (unsigned*)(winners + K_);        // [K_] winner positions
    float*              fred    = (float*)(spos + K_);              // [2]

    const int b    = blockIdx.x;
    const int tid  = threadIdx.x;
    const int lane = tid & 31;
    const int wid  = tid >> 5;

    // --- dtype sniff over the buffer's first NPOS odd words (both-dtype safe) ---
    const unsigned* lwords = (const unsigned*)labels_raw;
    int nz = 0;
    #pragma unroll 4
    for (int i = tid; i < NPOS; i += ST)
        nz |= (lwords[2 * i + 1] != 0u);
    const int is64 = !__syncthreads_or(nz);

    // logits for (b, s, a) classes {0,1} live at float2 index b*NPOS + p (p = s*A + a)
    const float2* pr2 = ((const float2*)g_logits) + (size_t)b * NPOS;
    const long long* lab64 = ((const long long*)labels_raw) + (size_t)b * NPOS;
    const int*       lab32 = ((const int*)labels_raw)       + (size_t)b * NPOS;

    auto get_label = [&](int i) -> int {
        return is64 ? (int)lab64[i] : lab32[i];
    };

    // --- Pass 1: count positives in this thread's contiguous chunk ---
    const int cbase = tid * SCH;
    unsigned cnt = 0;
    if (is64) {
        #pragma unroll 4
        for (int i = 0; i < SCH; ++i) cnt += (lab64[cbase + i] == 1);
    } else {
        #pragma unroll 4
        for (int i = 0; i < SCH; ++i) cnt += (lab32[cbase + i] == 1);
    }

    // --- Block exclusive scan (thread order == index order) ---
    unsigned inc = cnt;
    #pragma unroll
    for (int off = 1; off < 32; off <<= 1) {
        unsigned n = __shfl_up_sync(0xFFFFFFFFu, inc, off);
        if (lane >= off) inc += n;
    }
    unsigned* scanw = (unsigned*)wmax;   // reuse wmax region for warp sums
    if (lane == 31) scanw[wid] = inc;
    __syncthreads();
    if (wid == 0) {
        unsigned v = (lane < 8) ? scanw[lane] : 0u;
        #pragma unroll
        for (int off = 1; off < 8; off <<= 1) {
            unsigned n = __shfl_up_sync(0xFFFFFFFFu, v, off);
            if (lane >= off) v += n;
        }
        if (lane < 8) scanw[lane] = v;
    }
    __syncthreads();
    const unsigned excl  = inc - cnt + (wid ? scanw[wid - 1] : 0u);
    const unsigned total = scanw[7];
    __syncthreads();   // scanw (aliases wmax) must drain before fallback writes it

    if (total >= K_) {
        // --- FAST PATH: emit the K lowest-index positives by rank ---
        if (excl < K_ && cnt > 0) {
            unsigned rank = excl;
            for (int i = 0; i < SCH && rank < K_; ++i) {
                if (get_label(cbase + i) == 1) {
                    spos[rank++] = (unsigned)(cbase + i);
                }
            }
        }
        __syncthreads();
    } else {
        // --- FALLBACK: exact top-K via keys + iterative block argmax ---
        for (int i = tid; i < NPOS; i += ST) {
            unsigned vk;
            if (get_label(i) == 1) {
                vk = 0xFFFFFFFFu;
            } else {
                unsigned u = __float_as_uint(pr2[i].y);
                vk = (u & 0x80000000u) ? ~u : (u | 0x80000000u);
            }
            keys[i] = ((unsigned long long)vk << 32) |
                      (unsigned long long)(0xFFFFFFFFu - (unsigned)i);
        }
        __syncthreads();

        unsigned long long mymax = sel_scan_max(keys, tid);
        for (int k = 0; k < K_; ++k) {
            unsigned long long w = mymax;
            #pragma unroll
            for (int off = 16; off; off >>= 1) {
                unsigned long long o = __shfl_down_sync(0xFFFFFFFFu, w, off);
                if (o > w) w = o;
            }
            if (lane == 0) wmax[wid] = w;
            __syncthreads();
            if (tid == 0) {
                unsigned long long best = wmax[0];
                #pragma unroll
                for (int q = 1; q < ST / 32; ++q)
                    if (wmax[q] > best) best = wmax[q];
                winners[k] = best;
            }
            __syncthreads();
            unsigned idx = 0xFFFFFFFFu - (unsigned)(winners[k] & 0xFFFFFFFFull);
            if ((int)(idx & (ST - 1)) == tid) {
                keys[idx] = 0ull;
                mymax = sel_scan_max(keys, tid);
            }
        }
        __syncthreads();
        if (tid < K_)
            spos[tid] = 0xFFFFFFFFu - (unsigned)(winners[tid] & 0xFFFFFFFFull);
        __syncthreads();
    }

    // --- Outputs for the K samples (tid == k) ---
    float term = 0.f;
    if (tid < K_) {
        const int k = tid;
        unsigned p = spos[k];
        int s = (int)(p / 3u);
        int a = (int)(p - 3u * (unsigned)s);

        float* ot = out + OFF_TIDX + (size_t)(b * K_ + k) * 3;
        ot[0] = (float)b;
        ot[1] = (float)s;
        ot[2] = (float)a;

        float2 pr = pr2[p];
        out[OFF_CAND + b * K_ + k] = (pr.y > pr.x) ? 1.f : 0.f;

        int y = get_label((int)p);
        float xy = y ? pr.y : pr.x;
        float xo = y ? pr.x : pr.y;
        float m = MARGIN_ - xy + xo;
        term = (m > 0.f ? m : 0.f) * 0.5f;   // sum over j != y, divided by C=2
    }
    // Deterministic reduce of 64 terms (warps 0 and 1 fully active)
    if (tid < 64) {
        #pragma unroll
        for (int off = 16; off; off >>= 1)
            term += __shfl_down_sync(0xFFFFFFFFu, term, off);
        if (lane == 0) fred[wid] = term;
    }
    __syncthreads();

    // Last finishing block folds the B partials (fixed index order) into out[0].
    if (tid == 0) {
        g_losspart[b] = fred[0] + fred[1];
        __threadfence();
        unsigned prev = atomicAdd(&g_done, 1u);
        if (prev == B_ - 1) {
            float s = 0.f;
            #pragma unroll
            for (int q = 0; q < B_; ++q) s += g_losspart[q];
            out[0] = s / (float)(B_ * K_);
            g_done = 0u;   // reset for the next (graph-replayed) run
        }
    }
}

// ---------------------------------------------------------------------------
extern "C" void kernel_launch(void* const* d_in, const int* in_sizes, int n_in,
                              void* d_out, int out_size) {
    (void)in_sizes; (void)n_in; (void)out_size;
    const float4* X4     = (const float4*)d_in[0];
    const float*  W      = (const float*)d_in[1];
    const float*  bias   = (const float*)d_in[2];
    const void*   labels = d_in[3];
    float* out = (float*)d_out;

    cudaFuncSetAttribute(gemm_kernel,   cudaFuncAttributeMaxDynamicSharedMemorySize, GEMM_SMEM);
    cudaFuncSetAttribute(select_kernel, cudaFuncAttributeMaxDynamicSharedMemorySize, SEL_SMEM);

    gemm_kernel<<<ROWS_TOTAL / GT, GT, GEMM_SMEM>>>(X4, W, bias, out);
    select_kernel<<<B_, ST, SEL_SMEM>>>(labels, out);
}

// round 9
// speedup vs baseline: 1.5155x; 1.5155x over previous
#include <cuda_runtime.h>

// Problem constants
#define B_ 8
#define S_ 4096
#define D_ 1024
#define A_ 3
#define C_ 2
#define K_ 64
#define ROWS_TOTAL (B_ * S_)      // 32768
#define NPOS (S_ * A_)            // 12288 flat (seq, anchor) positions per batch
#define MARGIN_ 5.0f

// Output layout: [loss(1) | predict_label(B*S*A) | total_idx(B*K*3) | candidate_label(B*K)]
#define OFF_PRED 1
#define OFF_TIDX (1 + ROWS_TOTAL * A_)           // 98305
#define OFF_CAND (OFF_TIDX + B_ * K_ * 3)        // 99841

// Device scratch (no allocation allowed)
__device__ float    g_logits[ROWS_TOTAL * 6];    // (B*S, A*C) logits
__device__ float    g_losspart[B_];
__device__ unsigned g_done;                      // select-block completion counter

// ---------------------------------------------------------------------------
// Packed f32x2 helpers (Blackwell FFMA2 — PTX-only path)
// ---------------------------------------------------------------------------
__device__ __forceinline__ void ffma2(unsigned long long& a,
                                      unsigned long long x,
                                      unsigned long long w) {
    asm("fma.rn.f32x2 %0, %1, %2, %0;" : "+l"(a) : "l"(x), "l"(w));
}
__device__ __forceinline__ unsigned long long packf2(float lo, float hi) {
    unsigned long long r;
    asm("mov.b64 %0, {%1, %2};" : "=l"(r) : "f"(lo), "f"(hi));
    return r;
}
__device__ __forceinline__ void unpackf2(unsigned long long v, float& lo, float& hi) {
    asm("mov.b64 {%0, %1}, %2;" : "=f"(lo), "=f"(hi) : "l"(v));
}

// ---------------------------------------------------------------------------
// Kernel 1: logits = X @ W + b  and predict_label epilogue
// 8 lanes cooperate per row: lane l of an 8-lane group reads float4 j=g*8+l
// (128B fully-coalesced per row-segment, 4 rows per warp instruction).
// No smem staging of X — 32 independent LDG.128 per thread give the MLP, and
// ~6 blocks/SM (24KB static smem only) give the warps to hide DRAM latency.
// W transposed in smem (Wt[k][d]) so d-pairs are b64 for packed fma.rn.f32x2.
// Epilogue: 3-step shfl_xor reduction over the 8-lane group (deterministic).
// ---------------------------------------------------------------------------
#define GTH 256                   // threads per block
#define GR  (GTH / 8)             // 32 rows per block
#define GGRID (ROWS_TOTAL / GR)   // 1024 blocks

__global__ void __launch_bounds__(GTH) gemm_kernel(const float4* __restrict__ X4,
                                                   const float*  __restrict__ W,
                                                   const float*  __restrict__ bias,
                                                   float* __restrict__ out) {
    __shared__ float Wt[6 * D_];                       // 24576 B
    const unsigned long long* __restrict__ Wt64 = (const unsigned long long*)Wt;

    const int tid = threadIdx.x;

    // Stage W transposed: Wt[k][d] = W[d*6 + k]
    for (int i = tid; i < D_ * 6; i += GTH) {
        int d = i / 6;
        int k = i - 6 * d;
        Wt[k * D_ + d] = W[i];
    }
    __syncthreads();

    const int row = blockIdx.x * GR + (tid >> 3);
    const int l   = tid & 7;
    const float4* __restrict__ xr = X4 + (size_t)row * (D_ / 4);

    unsigned long long acc2[6];
    #pragma unroll
    for (int k = 0; k < 6; ++k) acc2[k] = 0ull;        // (+0.0f, +0.0f)

    #pragma unroll 8
    for (int g = 0; g < 32; ++g) {
        const int j = g * 8 + l;                       // float4 index in row
        float4 xv = __ldg(xr + j);
        unsigned long long x01 = packf2(xv.x, xv.y);
        unsigned long long x23 = packf2(xv.z, xv.w);
        #pragma unroll
        for (int k = 0; k < 6; ++k) {
            ulonglong2 wv = *reinterpret_cast<const ulonglong2*>(
                Wt64 + k * (D_ / 2) + 2 * j);          // 16B-aligned, 8-addr multicast
            ffma2(acc2[k], x01, wv.x);
            ffma2(acc2[k], x23, wv.y);
        }
    }

    // Combine lane-split partials, reduce across the 8-lane group
    float l6[6];
    #pragma unroll
    for (int k = 0; k < 6; ++k) {
        float lo, hi;
        unpackf2(acc2[k], lo, hi);
        l6[k] = lo + hi;
    }
    #pragma unroll
    for (int off = 1; off < 8; off <<= 1) {
        #pragma unroll
        for (int k = 0; k < 6; ++k)
            l6[k] += __shfl_xor_sync(0xFFFFFFFFu, l6[k], off);
    }

    if (l == 0) {
        float o6[6];
        #pragma unroll
        for (int k = 0; k < 6; ++k) o6[k] = l6[k] + __ldg(bias + k);

        float2* lg2 = (float2*)(g_logits + (size_t)row * 6);   // 24B stride, 8B aligned
        lg2[0] = make_float2(o6[0], o6[1]);
        lg2[1] = make_float2(o6[2], o6[3]);
        lg2[2] = make_float2(o6[4], o6[5]);

        float* op = out + OFF_PRED + (size_t)row * 3;
        op[0] = (o6[1] > o6[0]) ? 1.f : 0.f;   // argmax over C=2, tie -> 0
        op[1] = (o6[3] > o6[2]) ? 1.f : 0.f;
        op[2] = (o6[5] > o6[4]) ? 1.f : 0.f;
    }
}

// ---------------------------------------------------------------------------
// Kernel 2: per-batch exact top-K over lm[...,1] where positives (label==1)
// are forced to 2.0 (> any sigmoid), tie -> lower index first.
//
// FAST PATH (positives >= K): top-K == K lowest-index positives -> stream
// compaction with contiguous per-thread chunks + block exclusive scan.
// FALLBACK (positives < K): exact iterative block argmax over 64-bit keys
// (value_key << 32) | (0xFFFFFFFF - idx) — identical to jax.lax.top_k order.
//
// ST=1024 threads (12 positions/thread) + int4-vectorized label loads keep
// every serial phase short. Label dtype (int64 vs int32) sniffed from the
// buffer's odd 32-bit words (0/1 int64 labels -> all high halves zero).
// Last finishing block folds the B loss partials in fixed index order into
// out[0] and resets the counter (graph-replay deterministic).
// ---------------------------------------------------------------------------
#define ST 1024
#define SCH (NPOS / ST)           // 12 indices per thread chunk
#define NW  (ST / 32)             // 32 warps
#define SEL_SMEM (NPOS * 8 + NW * 8 + K_ * 8 + K_ * 4 + 16)

__device__ __forceinline__ unsigned long long sel_scan_max(
        const unsigned long long* keys, int tid) {
    unsigned long long m = 0ull;
    #pragma unroll
    for (int i = 0; i < SCH; ++i) {
        unsigned long long v = keys[tid + i * ST];
        if (v > m) m = v;
    }
    return m;
}

__global__ void __launch_bounds__(ST) select_kernel(const void* __restrict__ labels_raw,
                                                    float* __restrict__ out) {
    extern __shared__ char sraw[];
    unsigned long long* keys    = (unsigned long long*)sraw;        // [NPOS] (fallback only)
    unsigned long long* wmax    = keys + NPOS;                      // [NW]
    unsigned long long* winners = wmax + NW;                        // [K_]
    unsigned*           spos    = (unsigned*)(winners + K_);        // [K_]
    float*              fred    = (float*)(spos + K_);              // [2]

    const int b    = blockIdx.x;
    const int tid  = threadIdx.x;
    const int lane = tid & 31;
    const int wid  = tid >> 5;

    // --- dtype sniff: OR of the first NPOS odd 32-bit words, int4-vectorized
    // (first NPOS u64 = 98304 B = 6144 int4; odd words are .y/.w) ---
    const int4* lv = (const int4*)labels_raw;
    int nz = 0;
    #pragma unroll
    for (int w = 0; w < (NPOS / 2) / ST; ++w) {   // 6 iterations
        int4 v = lv[tid + w * ST];
        nz |= v.y | v.w;
    }
    const int is64 = !__syncthreads_or(nz);

    // logits for (b, s, a) classes {0,1} live at float2 index b*NPOS + p
    const float2* pr2 = ((const float2*)g_logits) + (size_t)b * NPOS;
    const long long* lab64 = ((const long long*)labels_raw) + (size_t)b * NPOS;
    const int*       lab32 = ((const int*)labels_raw)       + (size_t)b * NPOS;

    auto get_label = [&](int i) -> int {
        return is64 ? (int)lab64[i] : lab32[i];
    };

    // --- Pass 1: count positives in this thread's contiguous chunk (int4) ---
    const int cbase = tid * SCH;
    unsigned cnt = 0;
    if (is64) {
        const int4* p = (const int4*)(lab64 + cbase);   // 6 x int4 = 12 int64
        #pragma unroll
        for (int i = 0; i < SCH / 2; ++i) {
            int4 v = p[i];
            cnt += (v.x == 1) + (v.z == 1);             // high words known zero
        }
    } else {
        const int4* p = (const int4*)(lab32 + cbase);   // 3 x int4 = 12 int32
        #pragma unroll
        for (int i = 0; i < SCH / 4; ++i) {
            int4 v = p[i];
            cnt += (v.x == 1) + (v.y == 1) + (v.z == 1) + (v.w == 1);
        }
    }

    // --- Block exclusive scan (thread order == index order) ---
    unsigned inc = cnt;
    #pragma unroll
    for (int off = 1; off < 32; off <<= 1) {
        unsigned n = __shfl_up_sync(0xFFFFFFFFu, inc, off);
        if (lane >= off) inc += n;
    }
    unsigned* scanw = (unsigned*)wmax;   // reuse wmax region for warp sums
    if (lane == 31) scanw[wid] = inc;
    __syncthreads();
    if (wid == 0) {
        unsigned v = scanw[lane];        // NW == 32
        #pragma unroll
        for (int off = 1; off < 32; off <<= 1) {
            unsigned n = __shfl_up_sync(0xFFFFFFFFu, v, off);
            if (lane >= off) v += n;
        }
        scanw[lane] = v;
    }
    __syncthreads();
    const unsigned excl  = inc - cnt + (wid ? scanw[wid - 1] : 0u);
    const unsigned total = scanw[NW - 1];
    __syncthreads();   // scanw (aliases wmax) must drain before fallback writes it

    if (total >= K_) {
        // --- FAST PATH: emit the K lowest-index positives by rank ---
        if (excl < K_ && cnt > 0) {
            unsigned rank = excl;
            for (int i = 0; i < SCH && rank < K_; ++i) {
                if (get_label(cbase + i) == 1) {
                    spos[rank++] = (unsigned)(cbase + i);
                }
            }
        }
        __syncthreads();
    } else {
        // --- FALLBACK: exact top-K via keys + iterative block argmax ---
        for (int i = tid; i < NPOS; i += ST) {
            unsigned vk;
            if (get_label(i) == 1) {
                vk = 0xFFFFFFFFu;
            } else {
                unsigned u = __float_as_uint(pr2[i].y);
                vk = (u & 0x80000000u) ? ~u : (u | 0x80000000u);
            }
            keys[i] = ((unsigned long long)vk << 32) |
                      (unsigned long long)(0xFFFFFFFFu - (unsigned)i);
        }
        __syncthreads();

        unsigned long long mymax = sel_scan_max(keys, tid);
        for (int k = 0; k < K_; ++k) {
            unsigned long long w = mymax;
            #pragma unroll
            for (int off = 16; off; off >>= 1) {
                unsigned long long o = __shfl_down_sync(0xFFFFFFFFu, w, off);
                if (o > w) w = o;
            }
            if (lane == 0) wmax[wid] = w;
            __syncthreads();
            if (tid == 0) {
                unsigned long long best = wmax[0];
                #pragma unroll
                for (int q = 1; q < NW; ++q)
                    if (wmax[q] > best) best = wmax[q];
                winners[k] = best;
            }
            __syncthreads();
            unsigned idx = 0xFFFFFFFFu - (unsigned)(winners[k] & 0xFFFFFFFFull);
            if ((int)(idx & (ST - 1)) == tid) {
                keys[idx] = 0ull;
                mymax = sel_scan_max(keys, tid);
            }
        }
        __syncthreads();
        if (tid < K_)
            spos[tid] = 0xFFFFFFFFu - (unsigned)(winners[tid] & 0xFFFFFFFFull);
        __syncthreads();
    }

    // --- Outputs for the K samples (tid == k) ---
    float term = 0.f;
    if (tid < K_) {
        const int k = tid;
        unsigned p = spos[k];
        int s = (int)(p / 3u);
        int a = (int)(p - 3u * (unsigned)s);

        float* ot = out + OFF_TIDX + (size_t)(b * K_ + k) * 3;
        ot[0] = (float)b;
        ot[1] = (float)s;
        ot[2] = (float)a;

        float2 pr = pr2[p];
        out[OFF_CAND + b * K_ + k] = (pr.y > pr.x) ? 1.f : 0.f;

        int y = get_label((int)p);
        float xy = y ? pr.y : pr.x;
        float xo = y ? pr.x : pr.y;
        float m = MARGIN_ - xy + xo;
        term = (m > 0.f ? m : 0.f) * 0.5f;   // sum over j != y, divided by C=2
    }
    // Deterministic reduce of 64 terms (warps 0 and 1 fully active)
    if (tid < 64) {
        #pragma unroll
        for (int off = 16; off; off >>= 1)
            term += __shfl_down_sync(0xFFFFFFFFu, term, off);
        if (lane == 0) fred[wid] = term;
    }
    __syncthreads();

    // Last finishing block folds the B partials (fixed index order) into out[0].
    if (tid == 0) {
        g_losspart[b] = fred[0] + fred[1];
        __threadfence();
        unsigned prev = atomicAdd(&g_done, 1u);
        if (prev == B_ - 1) {
            float s = 0.f;
            #pragma unroll
            for (int q = 0; q < B_; ++q) s += g_losspart[q];
            out[0] = s / (float)(B_ * K_);
            g_done = 0u;   // reset for the next (graph-replayed) run
        }
    }
}

// ---------------------------------------------------------------------------
extern "C" void kernel_launch(void* const* d_in, const int* in_sizes, int n_in,
                              void* d_out, int out_size) {
    (void)in_sizes; (void)n_in; (void)out_size;
    const float4* X4     = (const float4*)d_in[0];
    const float*  W      = (const float*)d_in[1];
    const float*  bias   = (const float*)d_in[2];
    const void*   labels = d_in[3];
    float* out = (float*)d_out;

    cudaFuncSetAttribute(select_kernel, cudaFuncAttributeMaxDynamicSharedMemorySize, SEL_SMEM);

    gemm_kernel<<<GGRID, GTH>>>(X4, W, bias, out);
    select_kernel<<<B_, ST, SEL_SMEM>>>(labels, out);
}

// round 13
// speedup vs baseline: 1.9789x; 1.3058x over previous
#include <cuda_runtime.h>

// Problem constants
#define B_ 8
#define S_ 4096
#define D_ 1024
#define A_ 3
#define C_ 2
#define K_ 64
#define ROWS_TOTAL (B_ * S_)      // 32768
#define NPOS (S_ * A_)            // 12288 flat (seq, anchor) positions per batch
#define MARGIN_ 5.0f

// Output layout: [loss(1) | predict_label(B*S*A) | total_idx(B*K*3) | candidate_label(B*K)]
#define OFF_PRED 1
#define OFF_TIDX (1 + ROWS_TOTAL * A_)           // 98305
#define OFF_CAND (OFF_TIDX + B_ * K_ * 3)        // 99841

// Device scratch (no allocation allowed)
__device__ float    g_logits[ROWS_TOTAL * 6];    // (B*S, A*C) logits
__device__ float    g_losspart[B_];
__device__ unsigned g_done;                      // select-block completion counter

// ---------------------------------------------------------------------------
// Packed f32x2 helpers (Blackwell FFMA2 — PTX-only path)
// ---------------------------------------------------------------------------
__device__ __forceinline__ void ffma2(unsigned long long& a,
                                      unsigned long long x,
                                      unsigned long long w) {
    asm("fma.rn.f32x2 %0, %1, %2, %0;" : "+l"(a) : "l"(x), "l"(w));
}
__device__ __forceinline__ unsigned long long packf2(float lo, float hi) {
    unsigned long long r;
    asm("mov.b64 %0, {%1, %2};" : "=l"(r) : "f"(lo), "f"(hi));
    return r;
}
__device__ __forceinline__ void unpackf2(unsigned long long v, float& lo, float& hi) {
    asm("mov.b64 {%0, %1}, %2;" : "=f"(lo), "=f"(hi) : "l"(v));
}

// ---------------------------------------------------------------------------
// Kernel 1: logits = X @ W + b  and predict_label epilogue.
// Register-blocked: each thread computes the l-th d-slice (8 lanes/row-slice)
// of FOUR rows, so every W fetch from smem is amortized over 4 rows (W LDS
// lane-traffic /4 vs the 1-row version — was the crossbar bottleneck).
// X via __ldcs (single-use streaming), 4x128B segments per warp instruction.
// W transposed in smem (Wt[k][d]) so d-pairs are b64 for packed fma.rn.f32x2.
// Epilogue: 3-step shfl_xor over the 8-lane group; lanes 0-3 write row rr.
// ---------------------------------------------------------------------------
#define GTH 128                   // threads per block
#define RPT 4                     // rows per thread
#define GR  ((GTH / 8) * RPT)     // 64 rows per block
#define GGRID (ROWS_TOTAL / GR)   // 512 blocks

__global__ void __launch_bounds__(GTH) gemm_kernel(const float4* __restrict__ X4,
                                                   const float*  __restrict__ W,
                                                   const float*  __restrict__ bias,
                                                   float* __restrict__ out) {
    __shared__ float Wt[6 * D_];                       // 24576 B
    const unsigned long long* __restrict__ Wt64 = (const unsigned long long*)Wt;

    const int tid = threadIdx.x;

    // Stage W transposed: Wt[k][d] = W[d*6 + k]
    for (int i = tid; i < D_ * 6; i += GTH) {
        int d = i / 6;
        int k = i - 6 * d;
        Wt[k * D_ + d] = W[i];
    }
    __syncthreads();

    const int l  = tid & 7;                            // d-slice lane
    const int tg = tid >> 3;                           // thread-group id (16/block)
    const int r0 = blockIdx.x * GR + tg * RPT;
    const float4* __restrict__ xr0 = X4 + (size_t)r0 * (D_ / 4);

    unsigned long long acc2[RPT][6];
    #pragma unroll
    for (int rr = 0; rr < RPT; ++rr)
        #pragma unroll
        for (int k = 0; k < 6; ++k) acc2[rr][k] = 0ull;

    #pragma unroll 4
    for (int js = 0; js < 32; ++js) {
        const int j = js * 8 + l;                      // float4 index in row
        unsigned long long x01[RPT], x23[RPT];
        #pragma unroll
        for (int rr = 0; rr < RPT; ++rr) {
            float4 xv = __ldcs(xr0 + rr * (D_ / 4) + j);
            x01[rr] = packf2(xv.x, xv.y);
            x23[rr] = packf2(xv.z, xv.w);
        }
        #pragma unroll
        for (int k = 0; k < 6; ++k) {
            ulonglong2 wv = *reinterpret_cast<const ulonglong2*>(
                Wt64 + k * (D_ / 2) + 2 * j);          // 16B; 8 distinct/warp, 4x multicast
            #pragma unroll
            for (int rr = 0; rr < RPT; ++rr) {
                ffma2(acc2[rr][k], x01[rr], wv.x);
                ffma2(acc2[rr][k], x23[rr], wv.y);
            }
        }
    }

    // Combine lane-split halves, reduce across the 8-lane group (deterministic)
    float s[RPT][6];
    #pragma unroll
    for (int rr = 0; rr < RPT; ++rr)
        #pragma unroll
        for (int k = 0; k < 6; ++k) {
            float lo, hi;
            unpackf2(acc2[rr][k], lo, hi);
            s[rr][k] = lo + hi;
        }
    #pragma unroll
    for (int off = 1; off < 8; off <<= 1)
        #pragma unroll
        for (int rr = 0; rr < RPT; ++rr)
            #pragma unroll
            for (int k = 0; k < 6; ++k)
                s[rr][k] += __shfl_xor_sync(0xFFFFFFFFu, s[rr][k], off);

    // Lanes 0..3 each write one row (all lanes hold all sums post-xor)
    #pragma unroll
    for (int rr = 0; rr < RPT; ++rr) {
        if (l == rr) {
            const int row = r0 + rr;
            float o6[6];
            #pragma unroll
            for (int k = 0; k < 6; ++k) o6[k] = s[rr][k] + __ldg(bias + k);

            float2* lg2 = (float2*)(g_logits + (size_t)row * 6);
            lg2[0] = make_float2(o6[0], o6[1]);
            lg2[1] = make_float2(o6[2], o6[3]);
            lg2[2] = make_float2(o6[4], o6[5]);

            float* op = out + OFF_PRED + (size_t)row * 3;
            op[0] = (o6[1] > o6[0]) ? 1.f : 0.f;   // argmax over C=2, tie -> 0
            op[1] = (o6[3] > o6[2]) ? 1.f : 0.f;
            op[2] = (o6[5] > o6[4]) ? 1.f : 0.f;
        }
    }
}

// ---------------------------------------------------------------------------
// Kernel 2: per-batch exact top-K over lm[...,1] where positives (label==1)
// are forced to 2.0 (> any sigmoid), tie -> lower index first.
//
// FAST PATH (positives >= K): top-K == K lowest-index positives -> stream
// compaction with contiguous per-thread chunks + block exclusive scan.
// FALLBACK (positives < K): exact iterative block argmax over 64-bit keys
// (value_key << 32) | (0xFFFFFFFF - idx) — identical to jax.lax.top_k order.
//
// Dtype sniff is FUSED with the int32-side count: the per-batch int32-region
// [b*NPOS*4, +NPOS*4) is in-bounds under both dtype interpretations and
// 16B-aligned at an even word, so "all odd words zero" <=> buffer is int64
// (0/1 labels). Only the int64 case pays an extra load round trip.
// Last finishing block folds the B loss partials in fixed index order into
// out[0] and resets the counter (graph-replay deterministic).
// ---------------------------------------------------------------------------
#define ST 1024
#define SCH (NPOS / ST)           // 12 indices per thread chunk
#define NW  (ST / 32)             // 32 warps
#define SEL_SMEM (NPOS * 8 + NW * 8 + K_ * 8 + K_ * 4 + 16)

__device__ __forceinline__ unsigned long long sel_scan_max(
        const unsigned long long* keys, int tid) {
    unsigned long long m = 0ull;
    #pragma unroll
    for (int i = 0; i < SCH; ++i) {
        unsigned long long v = keys[tid + i * ST];
        if (v > m) m = v;
    }
    return m;
}

__global__ void __launch_bounds__(ST) select_kernel(const void* __restrict__ labels_raw,
                                                    float* __restrict__ out) {
    extern __shared__ char sraw[];
    unsigned long long* keys    = (unsigned long long*)sraw;        // [NPOS] (fallback only)
    unsigned long long* wmax    = keys + NPOS;                      // [NW]
    unsigned long long* winners = wmax + NW;                        // [K_]
    unsigned*           spos    = (unsigned*)(winners + K_);        // [K_]
    float*              fred    = (float*)(spos + K_);              // [2]

    const int b    = blockIdx.x;
    const int tid  = threadIdx.x;
    const int lane = tid & 31;
    const int wid  = tid >> 5;

    // --- fused sniff + int32 count over this batch's int32-region ---
    const int4* p32 = (const int4*)((const int*)labels_raw + (size_t)b * NPOS);
    int4 v0 = p32[tid * 3 + 0];
    int4 v1 = p32[tid * 3 + 1];
    int4 v2 = p32[tid * 3 + 2];
    int nz = v0.y | v0.w | v1.y | v1.w | v2.y | v2.w;
    unsigned cnt = (v0.x == 1) + (v0.y == 1) + (v0.z == 1) + (v0.w == 1)
                 + (v1.x == 1) + (v1.y == 1) + (v1.z == 1) + (v1.w == 1)
                 + (v2.x == 1) + (v2.y == 1) + (v2.z == 1) + (v2.w == 1);
    const int is64 = !__syncthreads_or(nz);

    const float2* pr2 = ((const float2*)g_logits) + (size_t)b * NPOS;
    const long long* lab64 = ((const long long*)labels_raw) + (size_t)b * NPOS;
    const int*       lab32 = ((const int*)labels_raw)       + (size_t)b * NPOS;

    auto get_label = [&](int i) -> int {
        return is64 ? (int)lab64[i] : lab32[i];
    };

    const int cbase = tid * SCH;
    if (is64) {
        // int64: recount from the u64-region chunk (only now known in-bounds)
        const int4* p = (const int4*)(lab64 + cbase);   // 6 x int4 = 12 int64
        cnt = 0;
        #pragma unroll
        for (int i = 0; i < SCH / 2; ++i) {
            int4 v = p[i];
            cnt += (v.x == 1) + (v.z == 1);             // high words known zero
        }
    }

    // --- Block exclusive scan (thread order == index order) ---
    unsigned inc = cnt;
    #pragma unroll
    for (int off = 1; off < 32; off <<= 1) {
        unsigned n = __shfl_up_sync(0xFFFFFFFFu, inc, off);
        if (lane >= off) inc += n;
    }
    unsigned* scanw = (unsigned*)wmax;   // reuse wmax region for warp sums
    if (lane == 31) scanw[wid] = inc;
    __syncthreads();
    if (wid == 0) {
        unsigned v = scanw[lane];        // NW == 32
        #pragma unroll
        for (int off = 1; off < 32; off <<= 1) {
            unsigned n = __shfl_up_sync(0xFFFFFFFFu, v, off);
            if (lane >= off) v += n;
        }
        scanw[lane] = v;
    }
    __syncthreads();
    const unsigned excl  = inc - cnt + (wid ? scanw[wid - 1] : 0u);
    const unsigned total = scanw[NW - 1];
    __syncthreads();   // scanw (aliases wmax) must drain before fallback writes it

    if (total >= K_) {
        // --- FAST PATH: emit the K lowest-index positives by rank ---
        if (excl < K_ && cnt > 0) {
            unsigned rank = excl;
            for (int i = 0; i < SCH && rank < K_; ++i) {
                if (get_label(cbase + i) == 1) {
                    spos[rank++] = (unsigned)(cbase + i);
                }
            }
        }
        __syncthreads();
    } else {
        // --- FALLBACK: exact top-K via keys + iterative block argmax ---
        for (int i = tid; i < NPOS; i += ST) {
            unsigned vk;
            if (get_label(i) == 1) {
                vk = 0xFFFFFFFFu;
            } else {
                unsigned u = __float_as_uint(pr2[i].y);
                vk = (u & 0x80000000u) ? ~u : (u | 0x80000000u);
            }
            keys[i] = ((unsigned long long)vk << 32) |
                      (unsigned long long)(0xFFFFFFFFu - (unsigned)i);
        }
        __syncthreads();

        unsigned long long mymax = sel_scan_max(keys, tid);
        for (int k = 0; k < K_; ++k) {
            unsigned long long w = mymax;
            #pragma unroll
            for (int off = 16; off; off >>= 1) {
                unsigned long long o = __shfl_down_sync(0xFFFFFFFFu, w, off);
                if (o > w) w = o;
            }
            if (lane == 0) wmax[wid] = w;
            __syncthreads();
            if (tid == 0) {
                unsigned long long best = wmax[0];
                #pragma unroll
                for (int q = 1; q < NW; ++q)
                    if (wmax[q] > best) best = wmax[q];
                winners[k] = best;
            }
            __syncthreads();
            unsigned idx = 0xFFFFFFFFu - (unsigned)(winners[k] & 0xFFFFFFFFull);
            if ((int)(idx & (ST - 1)) == tid) {
                keys[idx] = 0ull;
                mymax = sel_scan_max(keys, tid);
            }
        }
        __syncthreads();
        if (tid < K_)
            spos[tid] = 0xFFFFFFFFu - (unsigned)(winners[tid] & 0xFFFFFFFFull);
        __syncthreads();
    }

    // --- Outputs for the K samples (tid == k) ---
    float term = 0.f;
    if (tid < K_) {
        const int k = tid;
        unsigned p = spos[k];
        int s = (int)(p / 3u);
        int a = (int)(p - 3u * (unsigned)s);

        float* ot = out + OFF_TIDX + (size_t)(b * K_ + k) * 3;
        ot[0] = (float)b;
        ot[1] = (float)s;
        ot[2] = (float)a;

        float2 pr = pr2[p];
        out[OFF_CAND + b * K_ + k] = (pr.y > pr.x) ? 1.f : 0.f;

        int y = get_label((int)p);
        float xy = y ? pr.y : pr.x;
        float xo = y ? pr.x : pr.y;
        float m = MARGIN_ - xy + xo;
        term = (m > 0.f ? m : 0.f) * 0.5f;   // sum over j != y, divided by C=2
    }
    // Deterministic reduce of 64 terms (warps 0 and 1 fully active)
    if (tid < 64) {
        #pragma unroll
        for (int off = 16; off; off >>= 1)
            term += __shfl_down_sync(0xFFFFFFFFu, term, off);
        if (lane == 0) fred[wid] = term;
    }
    __syncthreads();

    // Last finishing block folds the B partials (fixed index order) into out[0].
    if (tid == 0) {
        g_losspart[b] = fred[0] + fred[1];
        __threadfence();
        unsigned prev = atomicAdd(&g_done, 1u);
        if (prev == B_ - 1) {
            float s = 0.f;
            #pragma unroll
            for (int q = 0; q < B_; ++q) s += g_losspart[q];
            out[0] = s / (float)(B_ * K_);
            g_done = 0u;   // reset for the next (graph-replayed) run
        }
    }
}

// ---------------------------------------------------------------------------
extern "C" void kernel_launch(void* const* d_in, const int* in_sizes, int n_in,
                              void* d_out, int out_size) {
    (void)in_sizes; (void)n_in; (void)out_size;
    const float4* X4     = (const float4*)d_in[0];
    const float*  W      = (const float*)d_in[1];
    const float*  bias   = (const float*)d_in[2];
    const void*   labels = d_in[3];
    float* out = (float*)d_out;

    cudaFuncSetAttribute(select_kernel, cudaFuncAttributeMaxDynamicSharedMemorySize, SEL_SMEM);

    gemm_kernel<<<GGRID, GTH>>>(X4, W, bias, out);
    select_kernel<<<B_, ST, SEL_SMEM>>>(labels, out);
}